// round 5
// baseline (speedup 1.0000x reference)
#include <cuda_runtime.h>
#include <cuda_fp16.h>
#include <math.h>
#include <stdint.h>

#define NN 100000
#define EE 3200000
#define HID 128
#define NCLS 40
#define MTILES 782   // ceil(100000/128)

// ---------------- scratch (device globals; no allocation) ----------------
__device__ int g_deg[NN];
__device__ int g_rowstart[NN];
__device__ int g_cursor[NN];
__device__ int g_excl[NN];
__device__ int g_bsum[128];
__device__ int g_csrcol[EE];
__device__ float  g_bufA[(size_t)NN * HID];    // Pa (self-projection, fp32)
__device__ __half g_bufB[(size_t)NN * HID];    // Pb (neighbor-projection, fp16)
__device__ __half g_h1[(size_t)NN * HID];      // layer-1 activations (fp16)
__device__ __half g_h2[(size_t)NN * HID];      // layer-2 activations (fp16)

__device__ __forceinline__ float tf32r(float x) {
    float y; asm("cvt.rna.tf32.f32 %0, %1;" : "=f"(y) : "f"(x)); return y;
}

__device__ __forceinline__ void mma_tf32(float* c, const uint32_t* a, const uint32_t* b) {
    asm volatile(
        "mma.sync.aligned.m16n8k8.row.col.f32.tf32.tf32.f32 "
        "{%0,%1,%2,%3}, {%4,%5,%6,%7}, {%8,%9}, {%0,%1,%2,%3};"
        : "+f"(c[0]), "+f"(c[1]), "+f"(c[2]), "+f"(c[3])
        : "r"(a[0]), "r"(a[1]), "r"(a[2]), "r"(a[3]), "r"(b[0]), "r"(b[1]));
}

// ---------------- CSR build ----------------
__global__ void k_zero() {
    int i = blockIdx.x * blockDim.x + threadIdx.x;
    if (i < NN) g_deg[i] = 0;
}
__global__ void k_hist(const int* __restrict__ rows) {
    int i = blockIdx.x * blockDim.x + threadIdx.x;
    if (i < EE) atomicAdd(&g_deg[rows[i]], 1);
}
__global__ void k_scan1() {
    __shared__ int s[1024];
    int gid = blockIdx.x * 1024 + threadIdx.x;
    int v = (gid < NN) ? g_deg[gid] : 0;
    s[threadIdx.x] = v;
    __syncthreads();
    #pragma unroll
    for (int off = 1; off < 1024; off <<= 1) {
        int t = (threadIdx.x >= off) ? s[threadIdx.x - off] : 0;
        __syncthreads();
        s[threadIdx.x] += t;
        __syncthreads();
    }
    if (gid < NN) g_excl[gid] = s[threadIdx.x] - v;
    if (threadIdx.x == 1023) g_bsum[blockIdx.x] = s[1023];
}
__global__ void k_scan2(int nb) {
    __shared__ int ws[4];
    int t = threadIdx.x;           // 128 threads
    int lane = t & 31, w = t >> 5;
    int v = (t < nb) ? g_bsum[t] : 0;
    int x = v;
    #pragma unroll
    for (int off = 1; off < 32; off <<= 1) {
        int y = __shfl_up_sync(0xffffffffu, x, off);
        if (lane >= off) x += y;
    }
    if (lane == 31) ws[w] = x;
    __syncthreads();
    int add = 0;
    for (int i = 0; i < w; i++) add += ws[i];
    if (t < nb) g_bsum[t] = x - v + add;   // exclusive scan of block sums
}
__global__ void k_scan3() {
    int gid = blockIdx.x * blockDim.x + threadIdx.x;
    if (gid < NN) {
        int rs = g_excl[gid] + g_bsum[gid >> 10];
        g_rowstart[gid] = rs;
        g_cursor[gid] = rs;
    }
}
__global__ void k_scatter(const int* __restrict__ rows, const int* __restrict__ cols) {
    int i = blockIdx.x * blockDim.x + threadIdx.x;
    if (i < EE) {
        int r = rows[i];
        int p = atomicAdd(&g_cursor[r], 1);
        g_csrcol[p] = cols[i];
    }
}

// ---------------- fused dual-half tf32 GEMM ----------------
// Computes Pa = A @ Wa^T (fp32 out) and Pb = A @ Wb^T (fp16 out) in one pass.
// Block tile 128 x 256 (N: 0-127 -> Pa, 128-255 -> Pb), 512 threads = 16 warps (4m x 4n),
// warp tile 32x64 via m16n8k8 tf32 MMAs. A read once.
template <int K, int LAYER>
__global__ void __launch_bounds__(512, 1) k_gemm_mma(const float* __restrict__ xin,
                                                     const float* __restrict__ W) {
    __shared__ float As[16][132];
    __shared__ float Bs[16][260];

    const int KW = 2 * K;
    const int mbase = blockIdx.x * 128;

    const int tid = threadIdx.x;
    const int w = tid >> 5;
    const int lane = tid & 31;
    const int wm = w & 3;        // warp m index -> rows wm*32
    const int wn = w >> 2;       // warp n index (0..3) -> cols wn*64
    const int gid = lane >> 2;   // 0..7
    const int tq = lane & 3;     // 0..3

    const int lrow = tid >> 2;   // 0..127 (A stage row)
    const int quad = tid & 3;    // k sub-quad (4 floats)

    float c[2][8][4];
    #pragma unroll
    for (int i = 0; i < 2; i++)
        #pragma unroll
        for (int j = 0; j < 8; j++)
            #pragma unroll
            for (int q = 0; q < 4; q++) c[i][j][q] = 0.f;

    const int mload = min(mbase + lrow, NN - 1);

    for (int kc = 0; kc < K; kc += 16) {
        // ---- stage A (128 x 16), tf32-rounded ----
        {
            int kb = quad * 4;
            if (LAYER == 1) {
                float4 v = *(const float4*)&xin[(size_t)mload * K + kc + kb];
                As[kb + 0][lrow] = tf32r(v.x);
                As[kb + 1][lrow] = tf32r(v.y);
                As[kb + 2][lrow] = tf32r(v.z);
                As[kb + 3][lrow] = tf32r(v.w);
            } else {
                uint2 raw = *(const uint2*)&g_h1[(size_t)mload * K + kc + kb];
                float2 f0 = __half22float2(*(__half2*)&raw.x);
                float2 f1 = __half22float2(*(__half2*)&raw.y);
                As[kb + 0][lrow] = f0.x;   // fp16 -> fp32 exact, fits tf32
                As[kb + 1][lrow] = f0.y;
                As[kb + 2][lrow] = f1.x;
                As[kb + 3][lrow] = f1.y;
            }
        }
        // ---- stage B (256 x 16): virtual rows 0-127 = Wa, 128-255 = Wb ----
        #pragma unroll
        for (int rep = 0; rep < 2; rep++) {
            int vrow = (tid >> 2) + rep * 128;
            int kb = quad * 4;
            const float* wsrc = (vrow < 128)
                ? &W[(size_t)vrow * KW + kc + kb]
                : &W[(size_t)(vrow - 128) * KW + K + kc + kb];
            float4 b = *(const float4*)wsrc;
            Bs[kb + 0][vrow] = tf32r(b.x);
            Bs[kb + 1][vrow] = tf32r(b.y);
            Bs[kb + 2][vrow] = tf32r(b.z);
            Bs[kb + 3][vrow] = tf32r(b.w);
        }
        __syncthreads();

        #pragma unroll
        for (int kk = 0; kk < 16; kk += 8) {
            uint32_t a[2][4];
            #pragma unroll
            for (int mt = 0; mt < 2; mt++) {
                int rb = wm * 32 + mt * 16;
                a[mt][0] = __float_as_uint(As[kk + tq][rb + gid]);
                a[mt][1] = __float_as_uint(As[kk + tq][rb + gid + 8]);
                a[mt][2] = __float_as_uint(As[kk + tq + 4][rb + gid]);
                a[mt][3] = __float_as_uint(As[kk + tq + 4][rb + gid + 8]);
            }
            #pragma unroll
            for (int nt = 0; nt < 8; nt++) {
                int nb = wn * 64 + nt * 8;
                uint32_t b[2];
                b[0] = __float_as_uint(Bs[kk + tq][nb + gid]);
                b[1] = __float_as_uint(Bs[kk + tq + 4][nb + gid]);
                mma_tf32(c[0][nt], a[0], b);
                mma_tf32(c[1][nt], a[1], b);
            }
        }
        __syncthreads();
    }

    // ---- epilogue: wn 0-1 -> Pa (fp32), wn 2-3 -> Pb (fp16) ----
    #pragma unroll
    for (int mt = 0; mt < 2; mt++) {
        #pragma unroll
        for (int nt = 0; nt < 8; nt++) {
            int row = mbase + wm * 32 + mt * 16 + gid;
            int col = wn * 64 + nt * 8 + 2 * tq;
            if (col < 128) {
                if (row < NN)
                    *(float2*)&g_bufA[(size_t)row * HID + col] =
                        make_float2(c[mt][nt][0], c[mt][nt][1]);
                if (row + 8 < NN)
                    *(float2*)&g_bufA[(size_t)(row + 8) * HID + col] =
                        make_float2(c[mt][nt][2], c[mt][nt][3]);
            } else {
                int cb = col - 128;
                if (row < NN) {
                    __half2 h = __floats2half2_rn(c[mt][nt][0], c[mt][nt][1]);
                    *(__half2*)&g_bufB[(size_t)row * HID + cb] = h;
                }
                if (row + 8 < NN) {
                    __half2 h = __floats2half2_rn(c[mt][nt][2], c[mt][nt][3]);
                    *(__half2*)&g_bufB[(size_t)(row + 8) * HID + cb] = h;
                }
            }
        }
    }
}

// ---------------- SpMM fused: h = relu(Pa + agg(Pb)/(deg+1)), warp per node ----------------
// Each lane owns 4 features (uint2 = 4 halves = 8B); 32 lanes x 8B = one 256B fp16 row.
template <int ROUND>
__global__ void __launch_bounds__(256) k_spmm() {
    const int tid = threadIdx.x;
    const int w = tid >> 5, lane = tid & 31;
    const int n = blockIdx.x * 8 + w;
    if (n >= NN) return;

    const int d = g_deg[n];
    const int s = g_rowstart[n];

    float acc0 = 0.f, acc1 = 0.f, acc2 = 0.f, acc3 = 0.f;

    for (int base = 0; base < d; base += 32) {
        int rem = d - base;
        int cj = (lane < rem) ? g_csrcol[s + base + lane] : 0;
        int cnt = min(32, rem);
        #pragma unroll 4
        for (int j = 0; j < cnt; j++) {
            int col = __shfl_sync(0xffffffffu, cj, j);
            uint2 v = *(const uint2*)&g_bufB[(size_t)col * HID + lane * 4];
            float2 f0 = __half22float2(*(__half2*)&v.x);
            float2 f1 = __half22float2(*(__half2*)&v.y);
            acc0 += f0.x; acc1 += f0.y;
            acc2 += f1.x; acc3 += f1.y;
        }
    }

    const float inv = 1.f / ((float)d + 1.0f);
    float4 pa = *(const float4*)&g_bufA[(size_t)n * HID + lane * 4];
    float r0 = fmaxf(pa.x + acc0 * inv, 0.f);
    float r1 = fmaxf(pa.y + acc1 * inv, 0.f);
    float r2 = fmaxf(pa.z + acc2 * inv, 0.f);
    float r3 = fmaxf(pa.w + acc3 * inv, 0.f);

    __half* out = (ROUND == 1) ? g_h1 : g_h2;
    uint2 o;
    *(__half2*)&o.x = __floats2half2_rn(r0, r1);
    *(__half2*)&o.y = __floats2half2_rn(r2, r3);
    *(uint2*)&out[(size_t)n * HID + lane * 4] = o;
}

// ---------------- MLP + log_softmax: one warp per node, 8 nodes/block ----------------
__global__ void k_mlp(const float* __restrict__ Wm, const float* __restrict__ bias,
                      float* __restrict__ out) {
    __shared__ float sW[NCLS * 129];
    __shared__ float sb[NCLS];
    __shared__ float sh[8][128];

    int tid = threadIdx.x;
    for (int idx = tid; idx < NCLS * 128; idx += 256) {
        int c = idx >> 7, k = idx & 127;
        sW[c * 129 + k] = Wm[idx];
    }
    if (tid < NCLS) sb[tid] = bias[tid];
    __syncthreads();

    int warp = tid >> 5, lane = tid & 31;
    int n = blockIdx.x * 8 + warp;

    {
        uint2 raw = *(const uint2*)&g_h2[(size_t)n * 128 + lane * 4];
        float2 f0 = __half22float2(*(__half2*)&raw.x);
        float2 f1 = __half22float2(*(__half2*)&raw.y);
        sh[warp][lane * 4 + 0] = f0.x;
        sh[warp][lane * 4 + 1] = f0.y;
        sh[warp][lane * 4 + 2] = f1.x;
        sh[warp][lane * 4 + 3] = f1.y;
    }
    __syncwarp();

    float v1 = sb[lane];
    float v2 = (lane < 8) ? sb[lane + 32] : -1e30f;

    const float* swr1 = &sW[lane * 129];
    #pragma unroll 8
    for (int k = 0; k < 128; k++) v1 += sh[warp][k] * swr1[k];
    if (lane < 8) {
        const float* swr2 = &sW[(lane + 32) * 129];
        #pragma unroll 8
        for (int k = 0; k < 128; k++) v2 += sh[warp][k] * swr2[k];
    }

    float mx = fmaxf(v1, v2);
    #pragma unroll
    for (int o = 16; o; o >>= 1) mx = fmaxf(mx, __shfl_xor_sync(0xffffffffu, mx, o));
    float s = expf(v1 - mx) + ((lane < 8) ? expf(v2 - mx) : 0.f);
    #pragma unroll
    for (int o = 16; o; o >>= 1) s += __shfl_xor_sync(0xffffffffu, s, o);
    float lg = logf(s);

    out[(size_t)n * NCLS + lane] = v1 - mx - lg;
    if (lane < 8) out[(size_t)n * NCLS + lane + 32] = v2 - mx - lg;
}

// ---------------- launch ----------------
extern "C" void kernel_launch(void* const* d_in, const int* in_sizes, int n_in,
                              void* d_out, int out_size) {
    const float* x  = (const float*)d_in[0];
    const float* W1 = (const float*)d_in[1];
    const float* W2 = (const float*)d_in[2];
    const float* mW = (const float*)d_in[3];
    const float* mb = (const float*)d_in[4];
    const int*   er = (const int*)d_in[5];
    const int*   ec = (const int*)d_in[6];
    float* out = (float*)d_out;

    // CSR build
    k_zero<<<(NN + 255) / 256, 256>>>();
    k_hist<<<(EE + 255) / 256, 256>>>(er);
    k_scan1<<<(NN + 1023) / 1024, 1024>>>();
    k_scan2<<<1, 128>>>((NN + 1023) / 1024);
    k_scan3<<<(NN + 255) / 256, 256>>>();
    k_scatter<<<(EE + 255) / 256, 256>>>(er, ec);

    // Layer 1: [Pa|Pb] = x @ W1^T (fused), then h1 = relu(Pa + agg(Pb)/(deg+1))
    k_gemm_mma<256, 1><<<MTILES, 512>>>(x, W1);
    k_spmm<1><<<(NN + 7) / 8, 256>>>();
    // Layer 2
    k_gemm_mma<128, 2><<<MTILES, 512>>>(x, W2);
    k_spmm<2><<<(NN + 7) / 8, 256>>>();
    // Head
    k_mlp<<<NN / 8, 256>>>(mW, mb, out);
}

// round 6
// speedup vs baseline: 1.5093x; 1.5093x over previous
#include <cuda_runtime.h>
#include <cuda_fp16.h>
#include <math.h>
#include <stdint.h>

#define NN 100000
#define EE 3200000
#define HID 128
#define NCLS 40
#define MTILES 782   // ceil(100000/128)

// ---------------- scratch (device globals; no allocation) ----------------
__device__ int g_deg[NN];
__device__ int g_rowstart[NN];
__device__ int g_cursor[NN];
__device__ int g_excl[NN];
__device__ int g_bsum[128];
__device__ int g_csrcol[EE];
__device__ float  g_bufA[(size_t)NN * HID];    // Pa (self-projection, fp32)
__device__ __half g_bufB[(size_t)NN * HID];    // Pb (neighbor-projection, fp16)
__device__ __half g_h1[(size_t)NN * HID];      // layer-1 activations (fp16)
__device__ __half g_h2[(size_t)NN * HID];      // layer-2 activations (fp16)

__device__ __forceinline__ float tf32r(float x) {
    float y; asm("cvt.rna.tf32.f32 %0, %1;" : "=f"(y) : "f"(x)); return y;
}

__device__ __forceinline__ void mma_tf32(float* c, const uint32_t* a, const uint32_t* b) {
    asm volatile(
        "mma.sync.aligned.m16n8k8.row.col.f32.tf32.tf32.f32 "
        "{%0,%1,%2,%3}, {%4,%5,%6,%7}, {%8,%9}, {%0,%1,%2,%3};"
        : "+f"(c[0]), "+f"(c[1]), "+f"(c[2]), "+f"(c[3])
        : "r"(a[0]), "r"(a[1]), "r"(a[2]), "r"(a[3]), "r"(b[0]), "r"(b[1]));
}

// ---------------- CSR build ----------------
__global__ void k_zero() {
    int i = blockIdx.x * blockDim.x + threadIdx.x;
    if (i < NN) g_deg[i] = 0;
}
__global__ void k_hist(const int* __restrict__ rows) {
    int i = blockIdx.x * blockDim.x + threadIdx.x;
    if (i < EE) atomicAdd(&g_deg[rows[i]], 1);
}
__global__ void k_scan1() {
    __shared__ int s[1024];
    int gid = blockIdx.x * 1024 + threadIdx.x;
    int v = (gid < NN) ? g_deg[gid] : 0;
    s[threadIdx.x] = v;
    __syncthreads();
    #pragma unroll
    for (int off = 1; off < 1024; off <<= 1) {
        int t = (threadIdx.x >= off) ? s[threadIdx.x - off] : 0;
        __syncthreads();
        s[threadIdx.x] += t;
        __syncthreads();
    }
    if (gid < NN) g_excl[gid] = s[threadIdx.x] - v;
    if (threadIdx.x == 1023) g_bsum[blockIdx.x] = s[1023];
}
__global__ void k_scan2(int nb) {
    __shared__ int ws[4];
    int t = threadIdx.x;           // 128 threads
    int lane = t & 31, w = t >> 5;
    int v = (t < nb) ? g_bsum[t] : 0;
    int x = v;
    #pragma unroll
    for (int off = 1; off < 32; off <<= 1) {
        int y = __shfl_up_sync(0xffffffffu, x, off);
        if (lane >= off) x += y;
    }
    if (lane == 31) ws[w] = x;
    __syncthreads();
    int add = 0;
    for (int i = 0; i < w; i++) add += ws[i];
    if (t < nb) g_bsum[t] = x - v + add;   // exclusive scan of block sums
}
__global__ void k_scan3() {
    int gid = blockIdx.x * blockDim.x + threadIdx.x;
    if (gid < NN) {
        int rs = g_excl[gid] + g_bsum[gid >> 10];
        g_rowstart[gid] = rs;
        g_cursor[gid] = rs;
    }
}
__global__ void k_scatter(const int* __restrict__ rows, const int* __restrict__ cols) {
    int i = blockIdx.x * blockDim.x + threadIdx.x;
    if (i < EE) {
        int r = rows[i];
        int p = atomicAdd(&g_cursor[r], 1);
        g_csrcol[p] = cols[i];
    }
}

// ---------------- mma.sync tf32 GEMM (R3-proven shape) ----------------
// Block tile 128x128, 256 threads = 8 warps (4m x 2n), warp tile 32x64.
// blockIdx.y = 0 -> Pa = A @ Wa^T (fp32 out); 1 -> Pb = A @ Wb^T (fp16 out).
template <int K, int LAYER>
__global__ void __launch_bounds__(256, 2) k_gemm_mma(const float* __restrict__ xin,
                                                     const float* __restrict__ W) {
    __shared__ float As[16][132];
    __shared__ float Bs[16][132];

    const int KW = 2 * K;
    const int koff = blockIdx.y * K;
    const int mbase = blockIdx.x * 128;

    const int tid = threadIdx.x;
    const int w = tid >> 5;
    const int lane = tid & 31;
    const int wm = w & 3;        // warp m index (0..3) -> rows wm*32
    const int wn = w >> 2;       // warp n index (0..1) -> cols wn*64
    const int gid = lane >> 2;   // 0..7
    const int tq = lane & 3;     // 0..3

    const int lrow = tid >> 1;   // 0..127 (load row)
    const int lhalf = tid & 1;   // which k-8 subchunk

    float c[2][8][4];
    #pragma unroll
    for (int i = 0; i < 2; i++)
        #pragma unroll
        for (int j = 0; j < 8; j++)
            #pragma unroll
            for (int q = 0; q < 4; q++) c[i][j][q] = 0.f;

    const int mload = min(mbase + lrow, NN - 1);

    for (int kc = 0; kc < K; kc += 16) {
        // stage A chunk (tf32-rounded), layout As[k][m]
        {
            int kb = lhalf * 8;
            if (LAYER == 1) {
                const float* src = &xin[(size_t)mload * K + kc + kb];
                float4 v0 = *(const float4*)(src);
                float4 v1 = *(const float4*)(src + 4);
                As[kb + 0][lrow] = tf32r(v0.x);
                As[kb + 1][lrow] = tf32r(v0.y);
                As[kb + 2][lrow] = tf32r(v0.z);
                As[kb + 3][lrow] = tf32r(v0.w);
                As[kb + 4][lrow] = tf32r(v1.x);
                As[kb + 5][lrow] = tf32r(v1.y);
                As[kb + 6][lrow] = tf32r(v1.z);
                As[kb + 7][lrow] = tf32r(v1.w);
            } else {
                uint4 raw = *(const uint4*)&g_h1[(size_t)mload * K + kc + kb];
                float2 f0 = __half22float2(*(__half2*)&raw.x);
                float2 f1 = __half22float2(*(__half2*)&raw.y);
                float2 f2 = __half22float2(*(__half2*)&raw.z);
                float2 f3 = __half22float2(*(__half2*)&raw.w);
                As[kb + 0][lrow] = f0.x;   // fp16 -> fp32 exact, fits tf32
                As[kb + 1][lrow] = f0.y;
                As[kb + 2][lrow] = f1.x;
                As[kb + 3][lrow] = f1.y;
                As[kb + 4][lrow] = f2.x;
                As[kb + 5][lrow] = f2.y;
                As[kb + 6][lrow] = f3.x;
                As[kb + 7][lrow] = f3.y;
            }

            const float* wsrc = &W[(size_t)lrow * KW + koff + kc + kb];
            float4 b0 = *(const float4*)(wsrc);
            float4 b1 = *(const float4*)(wsrc + 4);
            Bs[kb + 0][lrow] = tf32r(b0.x);
            Bs[kb + 1][lrow] = tf32r(b0.y);
            Bs[kb + 2][lrow] = tf32r(b0.z);
            Bs[kb + 3][lrow] = tf32r(b0.w);
            Bs[kb + 4][lrow] = tf32r(b1.x);
            Bs[kb + 5][lrow] = tf32r(b1.y);
            Bs[kb + 6][lrow] = tf32r(b1.z);
            Bs[kb + 7][lrow] = tf32r(b1.w);
        }
        __syncthreads();

        #pragma unroll
        for (int kk = 0; kk < 16; kk += 8) {
            uint32_t a[2][4];
            #pragma unroll
            for (int mt = 0; mt < 2; mt++) {
                int rb = wm * 32 + mt * 16;
                a[mt][0] = __float_as_uint(As[kk + tq][rb + gid]);
                a[mt][1] = __float_as_uint(As[kk + tq][rb + gid + 8]);
                a[mt][2] = __float_as_uint(As[kk + tq + 4][rb + gid]);
                a[mt][3] = __float_as_uint(As[kk + tq + 4][rb + gid + 8]);
            }
            #pragma unroll
            for (int nt = 0; nt < 8; nt++) {
                int nb = wn * 64 + nt * 8;
                uint32_t b[2];
                b[0] = __float_as_uint(Bs[kk + tq][nb + gid]);
                b[1] = __float_as_uint(Bs[kk + tq + 4][nb + gid]);
                mma_tf32(c[0][nt], a[0], b);
                mma_tf32(c[1][nt], a[1], b);
            }
        }
        __syncthreads();
    }

    // epilogue: y==0 -> Pa fp32, y==1 -> Pb fp16
    const bool toB = (blockIdx.y != 0);
    #pragma unroll
    for (int mt = 0; mt < 2; mt++) {
        #pragma unroll
        for (int nt = 0; nt < 8; nt++) {
            int row = mbase + wm * 32 + mt * 16 + gid;
            int col = wn * 64 + nt * 8 + 2 * tq;
            if (!toB) {
                if (row < NN)
                    *(float2*)&g_bufA[(size_t)row * HID + col] =
                        make_float2(c[mt][nt][0], c[mt][nt][1]);
                if (row + 8 < NN)
                    *(float2*)&g_bufA[(size_t)(row + 8) * HID + col] =
                        make_float2(c[mt][nt][2], c[mt][nt][3]);
            } else {
                if (row < NN)
                    *(__half2*)&g_bufB[(size_t)row * HID + col] =
                        __floats2half2_rn(c[mt][nt][0], c[mt][nt][1]);
                if (row + 8 < NN)
                    *(__half2*)&g_bufB[(size_t)(row + 8) * HID + col] =
                        __floats2half2_rn(c[mt][nt][2], c[mt][nt][3]);
            }
        }
    }
}

// ---------------- SpMM fused: h = relu(Pa + agg(Pb)/(deg+1)), warp per node ----------------
// Each lane owns 4 features (uint2 = 4 halves = 8B); 32 lanes x 8B = one 256B fp16 row.
template <int ROUND>
__global__ void __launch_bounds__(256) k_spmm() {
    const int tid = threadIdx.x;
    const int w = tid >> 5, lane = tid & 31;
    const int n = blockIdx.x * 8 + w;
    if (n >= NN) return;

    const int d = g_deg[n];
    const int s = g_rowstart[n];

    float acc0 = 0.f, acc1 = 0.f, acc2 = 0.f, acc3 = 0.f;

    for (int base = 0; base < d; base += 32) {
        int rem = d - base;
        int cj = (lane < rem) ? g_csrcol[s + base + lane] : 0;
        int cnt = min(32, rem);
        #pragma unroll 4
        for (int j = 0; j < cnt; j++) {
            int col = __shfl_sync(0xffffffffu, cj, j);
            uint2 v = *(const uint2*)&g_bufB[(size_t)col * HID + lane * 4];
            float2 f0 = __half22float2(*(__half2*)&v.x);
            float2 f1 = __half22float2(*(__half2*)&v.y);
            acc0 += f0.x; acc1 += f0.y;
            acc2 += f1.x; acc3 += f1.y;
        }
    }

    const float inv = 1.f / ((float)d + 1.0f);
    float4 pa = *(const float4*)&g_bufA[(size_t)n * HID + lane * 4];
    float r0 = fmaxf(pa.x + acc0 * inv, 0.f);
    float r1 = fmaxf(pa.y + acc1 * inv, 0.f);
    float r2 = fmaxf(pa.z + acc2 * inv, 0.f);
    float r3 = fmaxf(pa.w + acc3 * inv, 0.f);

    __half* out = (ROUND == 1) ? g_h1 : g_h2;
    uint2 o;
    *(__half2*)&o.x = __floats2half2_rn(r0, r1);
    *(__half2*)&o.y = __floats2half2_rn(r2, r3);
    *(uint2*)&out[(size_t)n * HID + lane * 4] = o;
}

// ---------------- MLP + log_softmax: one warp per node, 8 nodes/block ----------------
__global__ void k_mlp(const float* __restrict__ Wm, const float* __restrict__ bias,
                      float* __restrict__ out) {
    __shared__ float sW[NCLS * 129];
    __shared__ float sb[NCLS];
    __shared__ float sh[8][128];

    int tid = threadIdx.x;
    for (int idx = tid; idx < NCLS * 128; idx += 256) {
        int c = idx >> 7, k = idx & 127;
        sW[c * 129 + k] = Wm[idx];
    }
    if (tid < NCLS) sb[tid] = bias[tid];
    __syncthreads();

    int warp = tid >> 5, lane = tid & 31;
    int n = blockIdx.x * 8 + warp;

    {
        uint2 raw = *(const uint2*)&g_h2[(size_t)n * 128 + lane * 4];
        float2 f0 = __half22float2(*(__half2*)&raw.x);
        float2 f1 = __half22float2(*(__half2*)&raw.y);
        sh[warp][lane * 4 + 0] = f0.x;
        sh[warp][lane * 4 + 1] = f0.y;
        sh[warp][lane * 4 + 2] = f1.x;
        sh[warp][lane * 4 + 3] = f1.y;
    }
    __syncwarp();

    float v1 = sb[lane];
    float v2 = (lane < 8) ? sb[lane + 32] : -1e30f;

    const float* swr1 = &sW[lane * 129];
    #pragma unroll 8
    for (int k = 0; k < 128; k++) v1 += sh[warp][k] * swr1[k];
    if (lane < 8) {
        const float* swr2 = &sW[(lane + 32) * 129];
        #pragma unroll 8
        for (int k = 0; k < 128; k++) v2 += sh[warp][k] * swr2[k];
    }

    float mx = fmaxf(v1, v2);
    #pragma unroll
    for (int o = 16; o; o >>= 1) mx = fmaxf(mx, __shfl_xor_sync(0xffffffffu, mx, o));
    float s = expf(v1 - mx) + ((lane < 8) ? expf(v2 - mx) : 0.f);
    #pragma unroll
    for (int o = 16; o; o >>= 1) s += __shfl_xor_sync(0xffffffffu, s, o);
    float lg = logf(s);

    out[(size_t)n * NCLS + lane] = v1 - mx - lg;
    if (lane < 8) out[(size_t)n * NCLS + lane + 32] = v2 - mx - lg;
}

// ---------------- launch ----------------
extern "C" void kernel_launch(void* const* d_in, const int* in_sizes, int n_in,
                              void* d_out, int out_size) {
    const float* x  = (const float*)d_in[0];
    const float* W1 = (const float*)d_in[1];
    const float* W2 = (const float*)d_in[2];
    const float* mW = (const float*)d_in[3];
    const float* mb = (const float*)d_in[4];
    const int*   er = (const int*)d_in[5];
    const int*   ec = (const int*)d_in[6];
    float* out = (float*)d_out;

    // CSR build
    k_zero<<<(NN + 255) / 256, 256>>>();
    k_hist<<<(EE + 255) / 256, 256>>>(er);
    k_scan1<<<(NN + 1023) / 1024, 1024>>>();
    k_scan2<<<1, 128>>>((NN + 1023) / 1024);
    k_scan3<<<(NN + 255) / 256, 256>>>();
    k_scatter<<<(EE + 255) / 256, 256>>>(er, ec);

    // Layer 1: Pa = x@Wa^T (fp32), Pb = x@Wb^T (fp16), then h1 = relu(Pa + agg(Pb)/(deg+1))
    k_gemm_mma<256, 1><<<dim3(MTILES, 2), 256>>>(x, W1);
    k_spmm<1><<<(NN + 7) / 8, 256>>>();
    // Layer 2
    k_gemm_mma<128, 2><<<dim3(MTILES, 2), 256>>>(x, W2);
    k_spmm<2><<<(NN + 7) / 8, 256>>>();
    // Head
    k_mlp<<<NN / 8, 256>>>(mW, mb, out);
}

// round 9
// speedup vs baseline: 1.5868x; 1.0513x over previous
#include <cuda_runtime.h>
#include <cuda_fp16.h>
#include <math.h>
#include <stdint.h>

#define NN 100000
#define EE 3200000
#define HID 128
#define NCLS 40
#define MTILES 782   // ceil(100000/128)

// ---------------- scratch (device globals; no allocation) ----------------
__device__ int g_deg[NN];
__device__ int g_rowstart[NN];
__device__ int g_cursor[NN];
__device__ int g_excl[NN];
__device__ int g_bsum[128];
__device__ int g_csrcol[EE];
__device__ __half g_bufA[(size_t)NN * HID];    // Pa (self-projection, fp16)
__device__ __half g_bufB[(size_t)NN * HID];    // Pb (neighbor-projection, fp16)
__device__ __half g_h1[(size_t)NN * HID];      // layer-1 activations (fp16)
__device__ __half g_h2[(size_t)NN * HID];      // layer-2 activations (fp16)

__device__ __forceinline__ float tf32r(float x) {
    float y; asm("cvt.rna.tf32.f32 %0, %1;" : "=f"(y) : "f"(x)); return y;
}

__device__ __forceinline__ void mma_tf32(float* c, const uint32_t* a, const uint32_t* b) {
    asm volatile(
        "mma.sync.aligned.m16n8k8.row.col.f32.tf32.tf32.f32 "
        "{%0,%1,%2,%3}, {%4,%5,%6,%7}, {%8,%9}, {%0,%1,%2,%3};"
        : "+f"(c[0]), "+f"(c[1]), "+f"(c[2]), "+f"(c[3])
        : "r"(a[0]), "r"(a[1]), "r"(a[2]), "r"(a[3]), "r"(b[0]), "r"(b[1]));
}

// ---------------- CSR build ----------------
__global__ void k_zero() {
    int i = blockIdx.x * blockDim.x + threadIdx.x;
    if (i < NN) g_deg[i] = 0;
}
__global__ void k_hist(const int* __restrict__ rows) {
    int i = blockIdx.x * blockDim.x + threadIdx.x;
    if (i < EE) atomicAdd(&g_deg[rows[i]], 1);
}
__global__ void k_scan1() {
    __shared__ int s[1024];
    int gid = blockIdx.x * 1024 + threadIdx.x;
    int v = (gid < NN) ? g_deg[gid] : 0;
    s[threadIdx.x] = v;
    __syncthreads();
    #pragma unroll
    for (int off = 1; off < 1024; off <<= 1) {
        int t = (threadIdx.x >= off) ? s[threadIdx.x - off] : 0;
        __syncthreads();
        s[threadIdx.x] += t;
        __syncthreads();
    }
    if (gid < NN) g_excl[gid] = s[threadIdx.x] - v;
    if (threadIdx.x == 1023) g_bsum[blockIdx.x] = s[1023];
}
__global__ void k_scan2(int nb) {
    __shared__ int ws[4];
    int t = threadIdx.x;           // 128 threads
    int lane = t & 31, w = t >> 5;
    int v = (t < nb) ? g_bsum[t] : 0;
    int x = v;
    #pragma unroll
    for (int off = 1; off < 32; off <<= 1) {
        int y = __shfl_up_sync(0xffffffffu, x, off);
        if (lane >= off) x += y;
    }
    if (lane == 31) ws[w] = x;
    __syncthreads();
    int add = 0;
    for (int i = 0; i < w; i++) add += ws[i];
    if (t < nb) g_bsum[t] = x - v + add;   // exclusive scan of block sums
}
__global__ void k_scan3() {
    int gid = blockIdx.x * blockDim.x + threadIdx.x;
    if (gid < NN) {
        int rs = g_excl[gid] + g_bsum[gid >> 10];
        g_rowstart[gid] = rs;
        g_cursor[gid] = rs;
    }
}
__global__ void k_scatter(const int* __restrict__ rows, const int* __restrict__ cols) {
    int i = blockIdx.x * blockDim.x + threadIdx.x;
    if (i < EE) {
        int r = rows[i];
        int p = atomicAdd(&g_cursor[r], 1);
        g_csrcol[p] = cols[i];
    }
}

// ---------------- software-pipelined tf32 GEMM ----------------
// Block tile 128x128, 256 threads = 8 warps (4m x 2n), warp tile 32x64.
// blockIdx.y = 0 -> Pa = A @ Wa^T; 1 -> Pb = A @ Wb^T. Both fp16 out.
// Double-buffered SMEM; LDG of chunk ch+1 issued before MMAs of chunk ch.
template <int K, int LAYER>
__global__ void __launch_bounds__(256, 2) k_gemm_mma(const float* __restrict__ xin,
                                                     const float* __restrict__ W) {
    __shared__ float As[2][16][132];
    __shared__ float Bs[2][16][132];

    const int KW = 2 * K;
    const int koff = blockIdx.y * K;
    const int mbase = blockIdx.x * 128;

    const int tid = threadIdx.x;
    const int w = tid >> 5;
    const int lane = tid & 31;
    const int wm = w & 3;
    const int wn = w >> 2;
    const int gid = lane >> 2;
    const int tq = lane & 3;

    const int lrow = tid >> 1;   // 0..127
    const int kb = (tid & 1) * 8;

    float c[2][8][4];
    #pragma unroll
    for (int i = 0; i < 2; i++)
        #pragma unroll
        for (int j = 0; j < 8; j++)
            #pragma unroll
            for (int q = 0; q < 4; q++) c[i][j][q] = 0.f;

    const int mload = min(mbase + lrow, NN - 1);
    float ra[8], rb[8];

    // ---- chunk loader into registers ----
    auto ldg_chunk = [&](int kc) {
        if (LAYER == 1) {
            const float* src = &xin[(size_t)mload * K + kc + kb];
            float4 v0 = *(const float4*)(src);
            float4 v1 = *(const float4*)(src + 4);
            ra[0] = v0.x; ra[1] = v0.y; ra[2] = v0.z; ra[3] = v0.w;
            ra[4] = v1.x; ra[5] = v1.y; ra[6] = v1.z; ra[7] = v1.w;
        } else {
            uint4 raw = *(const uint4*)&g_h1[(size_t)mload * K + kc + kb];
            float2 f0 = __half22float2(*(__half2*)&raw.x);
            float2 f1 = __half22float2(*(__half2*)&raw.y);
            float2 f2 = __half22float2(*(__half2*)&raw.z);
            float2 f3 = __half22float2(*(__half2*)&raw.w);
            ra[0] = f0.x; ra[1] = f0.y; ra[2] = f1.x; ra[3] = f1.y;
            ra[4] = f2.x; ra[5] = f2.y; ra[6] = f3.x; ra[7] = f3.y;
        }
        const float* wsrc = &W[(size_t)lrow * KW + koff + kc + kb];
        float4 b0 = *(const float4*)(wsrc);
        float4 b1 = *(const float4*)(wsrc + 4);
        rb[0] = b0.x; rb[1] = b0.y; rb[2] = b0.z; rb[3] = b0.w;
        rb[4] = b1.x; rb[5] = b1.y; rb[6] = b1.z; rb[7] = b1.w;
    };
    auto sts_chunk = [&](int buf) {
        #pragma unroll
        for (int i = 0; i < 8; i++) As[buf][kb + i][lrow] = tf32r(ra[i]);
        #pragma unroll
        for (int i = 0; i < 8; i++) Bs[buf][kb + i][lrow] = tf32r(rb[i]);
    };
    auto compute = [&](int buf) {
        #pragma unroll
        for (int kk = 0; kk < 16; kk += 8) {
            uint32_t a[2][4];
            #pragma unroll
            for (int mt = 0; mt < 2; mt++) {
                int rbv = wm * 32 + mt * 16;
                a[mt][0] = __float_as_uint(As[buf][kk + tq][rbv + gid]);
                a[mt][1] = __float_as_uint(As[buf][kk + tq][rbv + gid + 8]);
                a[mt][2] = __float_as_uint(As[buf][kk + tq + 4][rbv + gid]);
                a[mt][3] = __float_as_uint(As[buf][kk + tq + 4][rbv + gid + 8]);
            }
            #pragma unroll
            for (int nt = 0; nt < 8; nt++) {
                int nb = wn * 64 + nt * 8;
                uint32_t b[2];
                b[0] = __float_as_uint(Bs[buf][kk + tq][nb + gid]);
                b[1] = __float_as_uint(Bs[buf][kk + tq + 4][nb + gid]);
                mma_tf32(c[0][nt], a[0], b);
                mma_tf32(c[1][nt], a[1], b);
            }
        }
    };

    constexpr int NCH = K / 16;
    ldg_chunk(0);
    sts_chunk(0);
    __syncthreads();
    for (int ch = 0; ch < NCH; ch++) {
        if (ch + 1 < NCH) ldg_chunk((ch + 1) * 16);   // LDG in flight during MMAs
        compute(ch & 1);
        if (ch + 1 < NCH) sts_chunk((ch + 1) & 1);
        __syncthreads();
    }

    __half* out = blockIdx.y ? g_bufB : g_bufA;
    #pragma unroll
    for (int mt = 0; mt < 2; mt++) {
        #pragma unroll
        for (int nt = 0; nt < 8; nt++) {
            int row = mbase + wm * 32 + mt * 16 + gid;
            int col = wn * 64 + nt * 8 + 2 * tq;
            if (row < NN)
                *(__half2*)&out[(size_t)row * HID + col] =
                    __floats2half2_rn(c[mt][nt][0], c[mt][nt][1]);
            if (row + 8 < NN)
                *(__half2*)&out[(size_t)(row + 8) * HID + col] =
                    __floats2half2_rn(c[mt][nt][2], c[mt][nt][3]);
        }
    }
}

// ---------------- SpMM fused: h = relu(Pa + agg(Pb)/(deg+1)), warp per node ----------------
template <int ROUND>
__global__ void __launch_bounds__(256) k_spmm() {
    const int tid = threadIdx.x;
    const int w = tid >> 5, lane = tid & 31;
    const int n = blockIdx.x * 8 + w;
    if (n >= NN) return;

    const int d = g_deg[n];
    const int s = g_rowstart[n];

    float acc0 = 0.f, acc1 = 0.f, acc2 = 0.f, acc3 = 0.f;

    for (int base = 0; base < d; base += 32) {
        int rem = d - base;
        int cj = (lane < rem) ? g_csrcol[s + base + lane] : 0;
        int cnt = min(32, rem);
        #pragma unroll 4
        for (int j = 0; j < cnt; j++) {
            int col = __shfl_sync(0xffffffffu, cj, j);
            uint2 v = *(const uint2*)&g_bufB[(size_t)col * HID + lane * 4];
            float2 f0 = __half22float2(*(__half2*)&v.x);
            float2 f1 = __half22float2(*(__half2*)&v.y);
            acc0 += f0.x; acc1 += f0.y;
            acc2 += f1.x; acc3 += f1.y;
        }
    }

    const float inv = 1.f / ((float)d + 1.0f);
    uint2 pa2 = *(const uint2*)&g_bufA[(size_t)n * HID + lane * 4];
    float2 p0 = __half22float2(*(__half2*)&pa2.x);
    float2 p1 = __half22float2(*(__half2*)&pa2.y);
    float r0 = fmaxf(p0.x + acc0 * inv, 0.f);
    float r1 = fmaxf(p0.y + acc1 * inv, 0.f);
    float r2 = fmaxf(p1.x + acc2 * inv, 0.f);
    float r3 = fmaxf(p1.y + acc3 * inv, 0.f);

    __half* out = (ROUND == 1) ? g_h1 : g_h2;
    uint2 o;
    *(__half2*)&o.x = __floats2half2_rn(r0, r1);
    *(__half2*)&o.y = __floats2half2_rn(r2, r3);
    *(uint2*)&out[(size_t)n * HID + lane * 4] = o;
}

// ---------------- MLP + log_softmax: persistent, one warp per node ----------------
#define MLP_BLOCKS 592
__global__ void __launch_bounds__(256) k_mlp(const float* __restrict__ Wm,
                                             const float* __restrict__ bias,
                                             float* __restrict__ out) {
    __shared__ float sW[NCLS * 129];
    __shared__ float sb[NCLS];
    __shared__ float sh[8][128];

    int tid = threadIdx.x;
    for (int idx = tid; idx < NCLS * 128; idx += 256) {
        int c = idx >> 7, k = idx & 127;
        sW[c * 129 + k] = Wm[idx];
    }
    if (tid < NCLS) sb[tid] = bias[tid];
    __syncthreads();

    int warp = tid >> 5, lane = tid & 31;
    const int NGRP = NN / 8;   // 12500

    for (int g = blockIdx.x; g < NGRP; g += MLP_BLOCKS) {
        int n = g * 8 + warp;

        {
            uint2 raw = *(const uint2*)&g_h2[(size_t)n * 128 + lane * 4];
            float2 f0 = __half22float2(*(__half2*)&raw.x);
            float2 f1 = __half22float2(*(__half2*)&raw.y);
            sh[warp][lane * 4 + 0] = f0.x;
            sh[warp][lane * 4 + 1] = f0.y;
            sh[warp][lane * 4 + 2] = f1.x;
            sh[warp][lane * 4 + 3] = f1.y;
        }
        __syncwarp();

        float v1 = sb[lane];
        float v2 = (lane < 8) ? sb[lane + 32] : -1e30f;

        const float* swr1 = &sW[lane * 129];
        #pragma unroll 8
        for (int k = 0; k < 128; k++) v1 += sh[warp][k] * swr1[k];
        if (lane < 8) {
            const float* swr2 = &sW[(lane + 32) * 129];
            #pragma unroll 8
            for (int k = 0; k < 128; k++) v2 += sh[warp][k] * swr2[k];
        }

        float mx = fmaxf(v1, v2);
        #pragma unroll
        for (int o = 16; o; o >>= 1) mx = fmaxf(mx, __shfl_xor_sync(0xffffffffu, mx, o));
        float s = expf(v1 - mx) + ((lane < 8) ? expf(v2 - mx) : 0.f);
        #pragma unroll
        for (int o = 16; o; o >>= 1) s += __shfl_xor_sync(0xffffffffu, s, o);
        float lg = logf(s);

        out[(size_t)n * NCLS + lane] = v1 - mx - lg;
        if (lane < 8) out[(size_t)n * NCLS + lane + 32] = v2 - mx - lg;
        __syncwarp();
    }
}

// ---------------- launch ----------------
extern "C" void kernel_launch(void* const* d_in, const int* in_sizes, int n_in,
                              void* d_out, int out_size) {
    const float* x  = (const float*)d_in[0];
    const float* W1 = (const float*)d_in[1];
    const float* W2 = (const float*)d_in[2];
    const float* mW = (const float*)d_in[3];
    const float* mb = (const float*)d_in[4];
    const int*   er = (const int*)d_in[5];
    const int*   ec = (const int*)d_in[6];
    float* out = (float*)d_out;

    // CSR build
    k_zero<<<(NN + 255) / 256, 256>>>();
    k_hist<<<(EE + 255) / 256, 256>>>(er);
    k_scan1<<<(NN + 1023) / 1024, 1024>>>();
    k_scan2<<<1, 128>>>((NN + 1023) / 1024);
    k_scan3<<<(NN + 255) / 256, 256>>>();
    k_scatter<<<(EE + 255) / 256, 256>>>(er, ec);

    // Layer 1: Pa = x@Wa^T, Pb = x@Wb^T (fp16), then h1 = relu(Pa + agg(Pb)/(deg+1))
    k_gemm_mma<256, 1><<<dim3(MTILES, 2), 256>>>(x, W1);
    k_spmm<1><<<(NN + 7) / 8, 256>>>();
    // Layer 2
    k_gemm_mma<128, 2><<<dim3(MTILES, 2), 256>>>(x, W2);
    k_spmm<2><<<(NN + 7) / 8, 256>>>();
    // Head
    k_mlp<<<MLP_BLOCKS, 256>>>(mW, mb, out);
}

// round 10
// speedup vs baseline: 1.8219x; 1.1482x over previous
#include <cuda_runtime.h>
#include <cuda_fp16.h>
#include <math.h>
#include <stdint.h>

#define NN 100000
#define EE 3200000
#define HID 128
#define NCLS 40
#define MTILES 782   // ceil(100000/128)
#define KP 40        // padded SMEM row length (halves)

// ---------------- scratch (device globals; no allocation) ----------------
__device__ int g_deg[NN];
__device__ int g_rowstart[NN];
__device__ int g_cursor[NN];
__device__ int g_excl[NN];
__device__ int g_bsum[128];
__device__ int g_csrcol[EE];
__device__ __half g_bufA[(size_t)NN * HID];    // Pa (self-projection, fp16)
__device__ __half g_bufB[(size_t)NN * HID];    // Pb (neighbor-projection, fp16)
__device__ __half g_h1[(size_t)NN * HID];      // layer-1 activations (fp16)
__device__ __half g_h2[(size_t)NN * HID];      // layer-2 activations (fp16)

__device__ __forceinline__ uint32_t h2bits(float a, float b) {
    __half2 h = __floats2half2_rn(a, b);
    return *(uint32_t*)&h;
}

__device__ __forceinline__ void mma_f16(float* c, const uint32_t* a, const uint32_t* b) {
    asm volatile(
        "mma.sync.aligned.m16n8k16.row.col.f32.f16.f16.f32 "
        "{%0,%1,%2,%3}, {%4,%5,%6,%7}, {%8,%9}, {%0,%1,%2,%3};"
        : "+f"(c[0]), "+f"(c[1]), "+f"(c[2]), "+f"(c[3])
        : "r"(a[0]), "r"(a[1]), "r"(a[2]), "r"(a[3]), "r"(b[0]), "r"(b[1]));
}

// ---------------- CSR build ----------------
__global__ void k_zero() {
    int i = blockIdx.x * blockDim.x + threadIdx.x;
    if (i < NN) g_deg[i] = 0;
}
__global__ void k_hist(const int* __restrict__ rows) {
    int i = blockIdx.x * blockDim.x + threadIdx.x;
    if (i < EE) atomicAdd(&g_deg[rows[i]], 1);
}
__global__ void k_scan1() {
    __shared__ int s[1024];
    int gid = blockIdx.x * 1024 + threadIdx.x;
    int v = (gid < NN) ? g_deg[gid] : 0;
    s[threadIdx.x] = v;
    __syncthreads();
    #pragma unroll
    for (int off = 1; off < 1024; off <<= 1) {
        int t = (threadIdx.x >= off) ? s[threadIdx.x - off] : 0;
        __syncthreads();
        s[threadIdx.x] += t;
        __syncthreads();
    }
    if (gid < NN) g_excl[gid] = s[threadIdx.x] - v;
    if (threadIdx.x == 1023) g_bsum[blockIdx.x] = s[1023];
}
__global__ void k_scan2(int nb) {
    __shared__ int ws[4];
    int t = threadIdx.x;           // 128 threads
    int lane = t & 31, w = t >> 5;
    int v = (t < nb) ? g_bsum[t] : 0;
    int x = v;
    #pragma unroll
    for (int off = 1; off < 32; off <<= 1) {
        int y = __shfl_up_sync(0xffffffffu, x, off);
        if (lane >= off) x += y;
    }
    if (lane == 31) ws[w] = x;
    __syncthreads();
    int add = 0;
    for (int i = 0; i < w; i++) add += ws[i];
    if (t < nb) g_bsum[t] = x - v + add;   // exclusive scan of block sums
}
__global__ void k_scan3() {
    int gid = blockIdx.x * blockDim.x + threadIdx.x;
    if (gid < NN) {
        int rs = g_excl[gid] + g_bsum[gid >> 10];
        g_rowstart[gid] = rs;
        g_cursor[gid] = rs;
    }
}
__global__ void k_scatter(const int* __restrict__ rows, const int* __restrict__ cols) {
    int i = blockIdx.x * blockDim.x + threadIdx.x;
    if (i < EE) {
        int r = rows[i];
        int p = atomicAdd(&g_cursor[r], 1);
        g_csrcol[p] = cols[i];
    }
}

// ---------------- fp16 mma GEMM (fp32 accumulate) ----------------
// Block tile 128x128, 256 threads = 8 warps (4m x 2n), warp tile 32x64 via m16n8k16.
// blockIdx.y = 0 -> Pa = A @ Wa^T; 1 -> Pb = A @ Wb^T. Both fp16 out.
// Double-buffered half SMEM (16-k chunks), [m][k]-major with 40-half padded rows.
template <int K, int LAYER>
__global__ void __launch_bounds__(256, 2) k_gemm_mma(const float* __restrict__ xin,
                                                     const float* __restrict__ W) {
    __shared__ __half As[2][128][KP];
    __shared__ __half Bs[2][128][KP];

    const int KW = 2 * K;
    const int koff = blockIdx.y * K;
    const int mbase = blockIdx.x * 128;

    const int tid = threadIdx.x;
    const int w = tid >> 5;
    const int lane = tid & 31;
    const int wm = w & 3;
    const int wn = w >> 2;
    const int gid = lane >> 2;   // 0..7
    const int tq = lane & 3;     // 0..3

    const int lrow = tid >> 1;        // 0..127 (stage row)
    const int kb = (tid & 1) * 8;     // half-offset within 16-k chunk

    float c[2][8][4];
    #pragma unroll
    for (int i = 0; i < 2; i++)
        #pragma unroll
        for (int j = 0; j < 8; j++)
            #pragma unroll
            for (int q = 0; q < 4; q++) c[i][j][q] = 0.f;

    const int mload = min(mbase + lrow, NN - 1);
    uint32_t ra[4], rb[4];   // 8 halves each, packed half2

    auto ldg_chunk = [&](int kc) {
        if (LAYER == 1) {
            const float* src = &xin[(size_t)mload * K + kc + kb];
            float4 v0 = *(const float4*)(src);
            float4 v1 = *(const float4*)(src + 4);
            ra[0] = h2bits(v0.x, v0.y);
            ra[1] = h2bits(v0.z, v0.w);
            ra[2] = h2bits(v1.x, v1.y);
            ra[3] = h2bits(v1.z, v1.w);
        } else {
            uint4 raw = *(const uint4*)&g_h1[(size_t)mload * K + kc + kb];
            ra[0] = raw.x; ra[1] = raw.y; ra[2] = raw.z; ra[3] = raw.w;
        }
        const float* wsrc = &W[(size_t)lrow * KW + koff + kc + kb];
        float4 b0 = *(const float4*)(wsrc);
        float4 b1 = *(const float4*)(wsrc + 4);
        rb[0] = h2bits(b0.x, b0.y);
        rb[1] = h2bits(b0.z, b0.w);
        rb[2] = h2bits(b1.x, b1.y);
        rb[3] = h2bits(b1.z, b1.w);
    };
    auto sts_chunk = [&](int buf) {
        *(uint4*)&As[buf][lrow][kb] = make_uint4(ra[0], ra[1], ra[2], ra[3]);
        *(uint4*)&Bs[buf][lrow][kb] = make_uint4(rb[0], rb[1], rb[2], rb[3]);
    };
    auto compute = [&](int buf) {
        uint32_t a[2][4];
        #pragma unroll
        for (int mt = 0; mt < 2; mt++) {
            int rbv = wm * 32 + mt * 16;
            a[mt][0] = *(const uint32_t*)&As[buf][rbv + gid][2 * tq];
            a[mt][1] = *(const uint32_t*)&As[buf][rbv + gid + 8][2 * tq];
            a[mt][2] = *(const uint32_t*)&As[buf][rbv + gid][2 * tq + 8];
            a[mt][3] = *(const uint32_t*)&As[buf][rbv + gid + 8][2 * tq + 8];
        }
        #pragma unroll
        for (int nt = 0; nt < 8; nt++) {
            int nb = wn * 64 + nt * 8;
            uint32_t b[2];
            b[0] = *(const uint32_t*)&Bs[buf][nb + gid][2 * tq];
            b[1] = *(const uint32_t*)&Bs[buf][nb + gid][2 * tq + 8];
            mma_f16(c[0][nt], a[0], b);
            mma_f16(c[1][nt], a[1], b);
        }
    };

    constexpr int NCH = K / 16;
    ldg_chunk(0);
    sts_chunk(0);
    __syncthreads();
    for (int ch = 0; ch < NCH; ch++) {
        if (ch + 1 < NCH) ldg_chunk((ch + 1) * 16);   // LDG in flight during MMAs
        compute(ch & 1);
        if (ch + 1 < NCH) sts_chunk((ch + 1) & 1);
        __syncthreads();
    }

    __half* out = blockIdx.y ? g_bufB : g_bufA;
    #pragma unroll
    for (int mt = 0; mt < 2; mt++) {
        #pragma unroll
        for (int nt = 0; nt < 8; nt++) {
            int row = mbase + wm * 32 + mt * 16 + gid;
            int col = wn * 64 + nt * 8 + 2 * tq;
            if (row < NN)
                *(__half2*)&out[(size_t)row * HID + col] =
                    __floats2half2_rn(c[mt][nt][0], c[mt][nt][1]);
            if (row + 8 < NN)
                *(__half2*)&out[(size_t)(row + 8) * HID + col] =
                    __floats2half2_rn(c[mt][nt][2], c[mt][nt][3]);
        }
    }
}

// ---------------- SpMM fused: h = relu(Pa + agg(Pb)/(deg+1)), warp per node ----------------
template <int ROUND>
__global__ void __launch_bounds__(256) k_spmm() {
    const int tid = threadIdx.x;
    const int w = tid >> 5, lane = tid & 31;
    const int n = blockIdx.x * 8 + w;
    if (n >= NN) return;

    const int d = g_deg[n];
    const int s = g_rowstart[n];

    float acc0 = 0.f, acc1 = 0.f, acc2 = 0.f, acc3 = 0.f;

    for (int base = 0; base < d; base += 32) {
        int rem = d - base;
        int cj = (lane < rem) ? g_csrcol[s + base + lane] : 0;
        int cnt = min(32, rem);
        #pragma unroll 4
        for (int j = 0; j < cnt; j++) {
            int col = __shfl_sync(0xffffffffu, cj, j);
            uint2 v = *(const uint2*)&g_bufB[(size_t)col * HID + lane * 4];
            float2 f0 = __half22float2(*(__half2*)&v.x);
            float2 f1 = __half22float2(*(__half2*)&v.y);
            acc0 += f0.x; acc1 += f0.y;
            acc2 += f1.x; acc3 += f1.y;
        }
    }

    const float inv = 1.f / ((float)d + 1.0f);
    uint2 pa2 = *(const uint2*)&g_bufA[(size_t)n * HID + lane * 4];
    float2 p0 = __half22float2(*(__half2*)&pa2.x);
    float2 p1 = __half22float2(*(__half2*)&pa2.y);
    float r0 = fmaxf(p0.x + acc0 * inv, 0.f);
    float r1 = fmaxf(p0.y + acc1 * inv, 0.f);
    float r2 = fmaxf(p1.x + acc2 * inv, 0.f);
    float r3 = fmaxf(p1.y + acc3 * inv, 0.f);

    __half* out = (ROUND == 1) ? g_h1 : g_h2;
    uint2 o;
    *(__half2*)&o.x = __floats2half2_rn(r0, r1);
    *(__half2*)&o.y = __floats2half2_rn(r2, r3);
    *(uint2*)&out[(size_t)n * HID + lane * 4] = o;
}

// ---------------- MLP + log_softmax: persistent, one warp per node ----------------
#define MLP_BLOCKS 592
__global__ void __launch_bounds__(256) k_mlp(const float* __restrict__ Wm,
                                             const float* __restrict__ bias,
                                             float* __restrict__ out) {
    __shared__ float sW[NCLS * 129];
    __shared__ float sb[NCLS];
    __shared__ float sh[8][128];

    int tid = threadIdx.x;
    for (int idx = tid; idx < NCLS * 128; idx += 256) {
        int c = idx >> 7, k = idx & 127;
        sW[c * 129 + k] = Wm[idx];
    }
    if (tid < NCLS) sb[tid] = bias[tid];
    __syncthreads();

    int warp = tid >> 5, lane = tid & 31;
    const int NGRP = NN / 8;   // 12500

    for (int g = blockIdx.x; g < NGRP; g += MLP_BLOCKS) {
        int n = g * 8 + warp;

        {
            uint2 raw = *(const uint2*)&g_h2[(size_t)n * 128 + lane * 4];
            float2 f0 = __half22float2(*(__half2*)&raw.x);
            float2 f1 = __half22float2(*(__half2*)&raw.y);
            sh[warp][lane * 4 + 0] = f0.x;
            sh[warp][lane * 4 + 1] = f0.y;
            sh[warp][lane * 4 + 2] = f1.x;
            sh[warp][lane * 4 + 3] = f1.y;
        }
        __syncwarp();

        float v1 = sb[lane];
        float v2 = (lane < 8) ? sb[lane + 32] : -1e30f;

        const float* swr1 = &sW[lane * 129];
        #pragma unroll 8
        for (int k = 0; k < 128; k++) v1 += sh[warp][k] * swr1[k];
        if (lane < 8) {
            const float* swr2 = &sW[(lane + 32) * 129];
            #pragma unroll 8
            for (int k = 0; k < 128; k++) v2 += sh[warp][k] * swr2[k];
        }

        float mx = fmaxf(v1, v2);
        #pragma unroll
        for (int o = 16; o; o >>= 1) mx = fmaxf(mx, __shfl_xor_sync(0xffffffffu, mx, o));
        float s = expf(v1 - mx) + ((lane < 8) ? expf(v2 - mx) : 0.f);
        #pragma unroll
        for (int o = 16; o; o >>= 1) s += __shfl_xor_sync(0xffffffffu, s, o);
        float lg = logf(s);

        out[(size_t)n * NCLS + lane] = v1 - mx - lg;
        if (lane < 8) out[(size_t)n * NCLS + lane + 32] = v2 - mx - lg;
        __syncwarp();
    }
}

// ---------------- launch ----------------
extern "C" void kernel_launch(void* const* d_in, const int* in_sizes, int n_in,
                              void* d_out, int out_size) {
    const float* x  = (const float*)d_in[0];
    const float* W1 = (const float*)d_in[1];
    const float* W2 = (const float*)d_in[2];
    const float* mW = (const float*)d_in[3];
    const float* mb = (const float*)d_in[4];
    const int*   er = (const int*)d_in[5];
    const int*   ec = (const int*)d_in[6];
    float* out = (float*)d_out;

    // CSR build
    k_zero<<<(NN + 255) / 256, 256>>>();
    k_hist<<<(EE + 255) / 256, 256>>>(er);
    k_scan1<<<(NN + 1023) / 1024, 1024>>>();
    k_scan2<<<1, 128>>>((NN + 1023) / 1024);
    k_scan3<<<(NN + 255) / 256, 256>>>();
    k_scatter<<<(EE + 255) / 256, 256>>>(er, ec);

    // Layer 1: Pa = x@Wa^T, Pb = x@Wb^T (fp16), then h1 = relu(Pa + agg(Pb)/(deg+1))
    k_gemm_mma<256, 1><<<dim3(MTILES, 2), 256>>>(x, W1);
    k_spmm<1><<<(NN + 7) / 8, 256>>>();
    // Layer 2
    k_gemm_mma<128, 2><<<dim3(MTILES, 2), 256>>>(x, W2);
    k_spmm<2><<<(NN + 7) / 8, 256>>>();
    // Head
    k_mlp<<<MLP_BLOCKS, 256>>>(mW, mb, out);
}